// round 1
// baseline (speedup 1.0000x reference)
#include <cuda_runtime.h>

#define NN 100000
#define NE 1600000
#define F_IN 128
#define HID 64
#define N_CLS 16

// ---------------- device scratch (allocation-free per rules) ----------------
__device__ int   g_cnt[NN];       // per-dst edge count (without self loop)
__device__ int   g_rowptr[NN];    // exclusive scan of g_cnt
__device__ int   g_cursor[NN];    // fill cursors
__device__ int   g_col[NE];       // CSR column (src) indices
__device__ float g_dinv[NN];      // rsqrt(deg+1)
__device__ float g_z[NN * HID];   // dinv-scaled XW buffer
__device__ float g_h[NN * HID];   // hidden activations
__device__ int   g_blksum[128];   // scan partials
__device__ int   g_is64;          // edge_index dtype flag

// ---------------- small utility kernels ----------------
__global__ void k_zero() {
    int i = blockIdx.x * blockDim.x + threadIdx.x;
    if (i < NN) { g_cnt[i] = 0; g_cursor[i] = 0; }
}

// Detect whether edge_index is int64 (high 32-bit words all zero) or int32.
__global__ void k_detect(const int* __restrict__ w) {
    int t = threadIdx.x;
    int nz = 0;
    for (int i = t; i < 512; i += 32) nz |= w[2 * i + 1];
    #pragma unroll
    for (int o = 16; o; o >>= 1) nz |= __shfl_xor_sync(0xffffffffu, nz, o);
    if (t == 0) g_is64 = (nz == 0) ? 1 : 0;
}

__device__ __forceinline__ int load_edge(const void* ei, long long idx) {
    if (g_is64) return (int)((const long long*)ei)[idx];
    return ((const int*)ei)[idx];
}

__global__ void k_count(const void* __restrict__ ei) {
    int i = blockIdx.x * blockDim.x + threadIdx.x;
    if (i < NE) {
        int d = load_edge(ei, (long long)NE + i);
        atomicAdd(&g_cnt[d], 1);
    }
}

__global__ void k_scan1() {
    __shared__ int s[1024];
    int t = threadIdx.x, i = blockIdx.x * 1024 + t;
    int v = (i < NN) ? g_cnt[i] : 0;
    s[t] = v; __syncthreads();
    #pragma unroll
    for (int off = 1; off < 1024; off <<= 1) {
        int x = (t >= off) ? s[t - off] : 0;
        __syncthreads();
        s[t] += x;
        __syncthreads();
    }
    if (i < NN) g_rowptr[i] = s[t] - v;   // exclusive
    if (t == 1023) g_blksum[blockIdx.x] = s[t];
}

__global__ void k_scan2(int nb) {
    __shared__ int s[128];
    int t = threadIdx.x;
    int v = (t < nb) ? g_blksum[t] : 0;
    s[t] = v; __syncthreads();
    #pragma unroll
    for (int off = 1; off < 128; off <<= 1) {
        int x = (t >= off) ? s[t - off] : 0;
        __syncthreads();
        s[t] += x;
        __syncthreads();
    }
    if (t < nb) g_blksum[t] = s[t] - v;
}

__global__ void k_scan3() {
    int i = blockIdx.x * blockDim.x + threadIdx.x;
    if (i < NN) g_rowptr[i] += g_blksum[i >> 10];
}

__global__ void k_dinv() {
    int i = blockIdx.x * blockDim.x + threadIdx.x;
    if (i < NN) g_dinv[i] = rsqrtf((float)(g_cnt[i] + 1));
}

__global__ void k_fill(const void* __restrict__ ei) {
    int i = blockIdx.x * blockDim.x + threadIdx.x;
    if (i < NE) {
        int s = load_edge(ei, i);
        int d = load_edge(ei, (long long)NE + i);
        int p = g_rowptr[d] + atomicAdd(&g_cursor[d], 1);
        g_col[p] = s;
    }
}

// ---------------- GEMM:  Z[row,:] = dinv[row] * (X[row,:] @ W) ----------------
// TM=TN=4 register blocking. X tile padded to K+1 floats/row (conflict-free).
template<int K, int COLS, int ROWS>
__global__ void k_gemm(const float* __restrict__ X, const float* __restrict__ W,
                       float* __restrict__ Z) {
    constexpr int TDX = COLS / 4;
    constexpr int TDY = ROWS / 4;
    constexpr int NT  = TDX * TDY;
    constexpr int KP  = K + 1;
    extern __shared__ float sm[];
    float* Ws = sm;                 // K * COLS
    float* Xs = sm + K * COLS;      // ROWS * KP

    int tid  = threadIdx.x;
    int row0 = blockIdx.x * ROWS;

    for (int idx = tid; idx < K * COLS; idx += NT) Ws[idx] = W[idx];
    for (int idx = tid; idx < ROWS * K; idx += NT) {
        int r = idx / K, k = idx - r * K;
        int gr = row0 + r;
        Xs[r * KP + k] = (gr < NN) ? X[(long long)gr * K + k] : 0.f;
    }
    __syncthreads();

    int tx = tid % TDX, ty = tid / TDX;
    float acc[4][4];
    #pragma unroll
    for (int a = 0; a < 4; a++)
        #pragma unroll
        for (int b = 0; b < 4; b++) acc[a][b] = 0.f;

    #pragma unroll 8
    for (int k = 0; k < K; k++) {
        float4 w = *(const float4*)&Ws[k * COLS + tx * 4];
        float x0 = Xs[(ty * 4 + 0) * KP + k];
        float x1 = Xs[(ty * 4 + 1) * KP + k];
        float x2 = Xs[(ty * 4 + 2) * KP + k];
        float x3 = Xs[(ty * 4 + 3) * KP + k];
        acc[0][0] += x0 * w.x; acc[0][1] += x0 * w.y; acc[0][2] += x0 * w.z; acc[0][3] += x0 * w.w;
        acc[1][0] += x1 * w.x; acc[1][1] += x1 * w.y; acc[1][2] += x1 * w.z; acc[1][3] += x1 * w.w;
        acc[2][0] += x2 * w.x; acc[2][1] += x2 * w.y; acc[2][2] += x2 * w.z; acc[2][3] += x2 * w.w;
        acc[3][0] += x3 * w.x; acc[3][1] += x3 * w.y; acc[3][2] += x3 * w.z; acc[3][3] += x3 * w.w;
    }

    #pragma unroll
    for (int a = 0; a < 4; a++) {
        int gr = row0 + ty * 4 + a;
        if (gr < NN) {
            float d = g_dinv[gr];
            float4 o = make_float4(acc[a][0] * d, acc[a][1] * d,
                                   acc[a][2] * d, acc[a][3] * d);
            *(float4*)&Z[(long long)gr * COLS + tx * 4] = o;
        }
    }
}

// ---------------- aggregation:  O[i] = act(dinv[i]*(Z[i] + sum_nbr Z[src]) + b) ----
// warp per node, 64 cols -> float2 per lane; col indices broadcast via shfl.
template<bool RELU>
__global__ void k_agg64(const float* __restrict__ Z, const float* __restrict__ bias,
                        float* __restrict__ O) {
    int w = (blockIdx.x * blockDim.x + threadIdx.x) >> 5;
    if (w >= NN) return;
    int lane = threadIdx.x & 31;
    int start = g_rowptr[w], m = g_cnt[w];

    float2 acc = *(const float2*)&Z[(long long)w * 64 + lane * 2];  // self loop
    for (int base = 0; base < m; base += 32) {
        int rem = m - base;
        int idx = (lane < rem) ? g_col[start + base + lane] : 0;
        int lim = rem < 32 ? rem : 32;
        for (int j = 0; j < lim; j++) {
            int s = __shfl_sync(0xffffffffu, idx, j);
            float2 v = *(const float2*)&Z[(long long)s * 64 + lane * 2];
            acc.x += v.x; acc.y += v.y;
        }
    }
    float d  = g_dinv[w];
    float ox = fmaf(d, acc.x, bias[lane * 2]);
    float oy = fmaf(d, acc.y, bias[lane * 2 + 1]);
    if (RELU) { ox = fmaxf(ox, 0.f); oy = fmaxf(oy, 0.f); }
    *(float2*)&O[(long long)w * 64 + lane * 2] = make_float2(ox, oy);
}

// 16-col final layer: 16 lanes per node, no relu.
__global__ void k_agg16(const float* __restrict__ Z, const float* __restrict__ bias,
                        float* __restrict__ O) {
    int g = (blockIdx.x * blockDim.x + threadIdx.x) >> 4;
    if (g >= NN) return;
    int lane = threadIdx.x & 15;
    int start = g_rowptr[g], m = g_cnt[g];

    float acc = Z[(long long)g * 16 + lane];   // self loop
    for (int base = 0; base < m; base += 16) {
        int rem = m - base;
        int idx = (lane < rem) ? g_col[start + base + lane] : 0;
        int lim = rem < 16 ? rem : 16;
        for (int j = 0; j < lim; j++) {
            int s = __shfl_sync(0xffffffffu, idx, j, 16);
            acc += Z[(long long)s * 16 + lane];
        }
    }
    O[(long long)g * 16 + lane] = fmaf(g_dinv[g], acc, bias[lane]);
}

// ---------------- launch ----------------
extern "C" void kernel_launch(void* const* d_in, const int* in_sizes, int n_in,
                              void* d_out, int out_size) {
    const float* x  = (const float*)d_in[0];
    const void*  ei = d_in[1];                 // int64 or int32 (detected on device)
    const float* W1 = (const float*)d_in[2];
    const float* b1 = (const float*)d_in[3];
    const float* W2 = (const float*)d_in[4];
    const float* b2 = (const float*)d_in[5];
    const float* W3 = (const float*)d_in[6];
    const float* b3 = (const float*)d_in[7];
    float* out = (float*)d_out;

    void *pz, *ph;
    cudaGetSymbolAddress(&pz, g_z);
    cudaGetSymbolAddress(&ph, g_h);
    float* Z = (float*)pz;
    float* H = (float*)ph;

    const int smem1 = (F_IN * HID + HID * (F_IN + 1)) * 4;       // 65792 B
    const int smem2 = (HID * HID + HID * (HID + 1)) * 4;         // 33024 B
    const int smem3 = (HID * N_CLS + 128 * (HID + 1)) * 4;       // 37376 B
    cudaFuncSetAttribute(k_gemm<F_IN, HID, 64>,
                         cudaFuncAttributeMaxDynamicSharedMemorySize, smem1);

    // graph structure + normalization (recomputed every call; no caching)
    k_zero<<<(NN + 255) / 256, 256>>>();
    k_detect<<<1, 32>>>((const int*)ei);
    k_count<<<(NE + 255) / 256, 256>>>(ei);
    k_scan1<<<(NN + 1023) / 1024, 1024>>>();
    k_scan2<<<1, 128>>>((NN + 1023) / 1024);
    k_scan3<<<(NN + 255) / 256, 256>>>();
    k_dinv<<<(NN + 255) / 256, 256>>>();
    k_fill<<<(NE + 255) / 256, 256>>>(ei);

    // layer 1: 128 -> 64, relu
    k_gemm<F_IN, HID, 64><<<(NN + 63) / 64, 256, smem1>>>(x, W1, Z);
    k_agg64<true><<<(NN * 32 + 255) / 256, 256>>>(Z, b1, H);

    // layer 2: 64 -> 64, relu
    k_gemm<HID, HID, 64><<<(NN + 63) / 64, 256, smem2>>>(H, W2, Z);
    k_agg64<true><<<(NN * 32 + 255) / 256, 256>>>(Z, b2, H);

    // layer 3: 64 -> 16, no relu
    k_gemm<HID, N_CLS, 128><<<(NN + 127) / 128, 128, smem3>>>(H, W3, Z);
    k_agg16<<<(NN * 16 + 255) / 256, 256>>>(Z, b3, out);
}